// round 1
// baseline (speedup 1.0000x reference)
#include <cuda_runtime.h>

#define DIMN 64
#define RBFN 64
#define HN   128          // 2*dim
#define NCAP 100000

// Scratch: per-node precomputed partial products of eu_w1 (src rows / dst rows)
__device__ float g_pre_a[(size_t)NCAP * HN];
__device__ float g_pre_b[(size_t)NCAP * HN];

typedef unsigned long long u64;

__device__ __forceinline__ u64 pack2(float lo, float hi) {
    u64 r; asm("mov.b64 %0,{%1,%2};" : "=l"(r) : "f"(lo), "f"(hi)); return r;
}
__device__ __forceinline__ float2 unpack2(u64 v) {
    float2 f; asm("mov.b64 {%0,%1},%2;" : "=f"(f.x), "=f"(f.y) : "l"(v)); return f;
}
__device__ __forceinline__ u64 ffma2(u64 a, u64 b, u64 c) {
    u64 d; asm("fma.rn.f32x2 %0,%1,%2,%3;" : "=l"(d) : "l"(a), "l"(b), "l"(c)); return d;
}
// shifted softplus: log(1+e^x) - log(2) = max(x,0) + log(0.5 + 0.5*e^{-|x|})
__device__ __forceinline__ float sspf(float x) {
    float u = __expf(-fabsf(x));
    return fmaxf(x, 0.0f) + __logf(fmaf(0.5f, u, 0.5f));
}

// ---- register-blocked tile GEMMs ------------------------------------------
// xT: [K][64] (pitch 64, transposed activations), w: [K][NJ] row-major in smem
// thread computes 4 e-rows (e0..e0+3) x (8 or 4) j-cols, f32x2-packed.

template<bool SWZ>
__device__ __forceinline__ void gemm_j8(const float* __restrict__ xT,
                                        const float* __restrict__ w,
                                        int e0, int j0, u64 acc[4][4]) {
#pragma unroll 4
    for (int k = 0; k < 64; k++) {
        int es = SWZ ? (e0 ^ (((k >> 2) & 7) << 2)) : e0;
        float4 xv = *(const float4*)(xT + k * 64 + es);
        const float* wr = w + k * 128 + j0;
        ulonglong2 wa = *(const ulonglong2*)(wr);
        ulonglong2 wb = *(const ulonglong2*)(wr + 4);
        u64 wd[4] = { wa.x, wa.y, wb.x, wb.y };
        u64 xd[4] = { pack2(xv.x, xv.x), pack2(xv.y, xv.y),
                      pack2(xv.z, xv.z), pack2(xv.w, xv.w) };
#pragma unroll
        for (int i = 0; i < 4; i++)
#pragma unroll
            for (int j = 0; j < 4; j++)
                acc[i][j] = ffma2(xd[i], wd[j], acc[i][j]);
    }
}

template<int K>
__device__ __forceinline__ void gemm_j4(const float* __restrict__ xT,
                                        const float* __restrict__ w,
                                        int e0, int j0, u64 acc[4][2]) {
#pragma unroll 4
    for (int k = 0; k < K; k++) {
        float4 xv = *(const float4*)(xT + k * 64 + e0);
        ulonglong2 wa = *(const ulonglong2*)(w + k * 64 + j0);
        u64 xd[4] = { pack2(xv.x, xv.x), pack2(xv.y, xv.y),
                      pack2(xv.z, xv.z), pack2(xv.w, xv.w) };
#pragma unroll
        for (int i = 0; i < 4; i++) {
            acc[i][0] = ffma2(xd[i], wa.x, acc[i][0]);
            acc[i][1] = ffma2(xd[i], wa.y, acc[i][1]);
        }
    }
}

// ---- node precompute: g_pre_a[n] = nf[n] @ eu_w1[0:64], g_pre_b = @ eu_w1[64:128]
__global__ void __launch_bounds__(256, 1)
node_pre_kernel(const float* __restrict__ node_feats,
                const float* __restrict__ eu_w1, int N) {
    extern __shared__ float sm[];
    float* sW  = sm;            // [64][128]
    float* sXT = sm + 8192;     // [64][64] node feats transposed
    const int tid = threadIdx.x;
    const int half = blockIdx.y;
    for (int i = tid; i < 64 * 128; i += 256)
        sW[i] = eu_w1[(half * 64 + (i >> 7)) * 128 + (i & 127)];
    const int base = blockIdx.x * 64;
#pragma unroll
    for (int i = 0; i < 4; i++) {
        int lin = tid + 256 * i;
        int n = lin >> 4, kq = lin & 15;
        int g = base + n;
        float4 v = make_float4(0.f, 0.f, 0.f, 0.f);
        if (g < N) v = *(const float4*)(node_feats + (size_t)g * 64 + kq * 4);
        sXT[(kq * 4 + 0) * 64 + n] = v.x;
        sXT[(kq * 4 + 1) * 64 + n] = v.y;
        sXT[(kq * 4 + 2) * 64 + n] = v.z;
        sXT[(kq * 4 + 3) * 64 + n] = v.w;
    }
    __syncthreads();
    const int tx = tid & 15, ty = tid >> 4;
    const int n0 = tx * 4, j0 = ty * 8;
    u64 acc[4][4];
#pragma unroll
    for (int i = 0; i < 4; i++) { acc[i][0] = 0; acc[i][1] = 0; acc[i][2] = 0; acc[i][3] = 0; }
    gemm_j8<false>(sXT, sW, n0, j0, acc);
    float* outp = half ? g_pre_b : g_pre_a;
#pragma unroll
    for (int i = 0; i < 4; i++) {
        int g = base + n0 + i;
        if (g < N) {
            float2 v0 = unpack2(acc[i][0]), v1 = unpack2(acc[i][1]);
            float2 v2 = unpack2(acc[i][2]), v3 = unpack2(acc[i][3]);
            float* op = outp + (size_t)g * HN + j0;
            *(float4*)(op)     = make_float4(v0.x, v0.y, v1.x, v1.y);
            *(float4*)(op + 4) = make_float4(v2.x, v2.y, v3.x, v3.y);
        }
    }
}

// ---- fused edge pipeline: layer1 -> new_edge -> pe MLP -> atomic segment-sum
#define EDGE_SMEM_FLOATS 45504

__global__ void __launch_bounds__(256, 1)
edge_kernel(const float* __restrict__ edge_feats,
            const int* __restrict__ srcp, const int* __restrict__ dstp,
            const float* __restrict__ eu_w1, const float* __restrict__ eu_b1,
            const float* __restrict__ eu_w2, const float* __restrict__ eu_b2,
            const float* __restrict__ pe_w1, const float* __restrict__ pe_b1,
            const float* __restrict__ pe_w2, const float* __restrict__ pe_b2,
            float* __restrict__ agg, float* __restrict__ out_edge,
            int E, int numTiles) {
    extern __shared__ float sm[];
    float* sW1c = sm;             // [64][128]  rbf rows of eu_w1
    float* sW2  = sm + 8192;      // [128][64]
    float* sPe1 = sm + 16384;     // [64][64]
    float* sPe2 = sm + 20480;     // [64][64]
    float* sB1  = sm + 24576;     // 128
    float* sB2  = sm + 24704;     // 64
    float* sPb1 = sm + 24768;     // 64
    float* sPb2 = sm + 24832;     // 64
    int*   sIdx = (int*)(sm + 24896); // src[64], dst[64]
    float* sX   = sm + 25024;     // [64][64]  rbf transposed, XOR-swizzled
    float* sH1  = sm + 29120;     // [128][64] ssp(h1) transposed
    float* sNE  = sm + 37312;     // [64][64]  new_edge transposed
    float* sT   = sm + 41408;     // [64][64]

    const int tid = threadIdx.x;
    for (int i = tid; i < 64 * 128; i += 256)
        sW1c[i] = eu_w1[(128 + (i >> 7)) * 128 + (i & 127)];
    for (int i = tid; i < 128 * 64; i += 256) sW2[i] = eu_w2[i];
    for (int i = tid; i < 64 * 64; i += 256) { sPe1[i] = pe_w1[i]; sPe2[i] = pe_w2[i]; }
    if (tid < 128) sB1[tid] = eu_b1[tid];
    if (tid < 64) { sB2[tid] = eu_b2[tid]; sPb1[tid] = pe_b1[tid]; sPb2[tid] = pe_b2[tid]; }
    __syncthreads();

    const int tx = tid & 15, ty = tid >> 4;
    const int e0 = tx * 4;

    for (int tile = blockIdx.x; tile < numTiles; tile += gridDim.x) {
        const int base = tile * 64;
        if (tid < 64)        { int g = base + tid;      sIdx[tid] = (g < E) ? srcp[g] : 0; }
        else if (tid < 128)  { int g = base + tid - 64; sIdx[tid] = (g < E) ? dstp[g] : 0; }
#pragma unroll
        for (int i = 0; i < 4; i++) {
            int lin = tid + 256 * i;
            int e = lin >> 4, kq = lin & 15;
            int g = base + e;
            float4 v = make_float4(0.f, 0.f, 0.f, 0.f);
            if (g < E) v = *(const float4*)(edge_feats + (size_t)g * RBFN + kq * 4);
            int es = e ^ ((kq & 7) << 2);
            sX[(kq * 4 + 0) * 64 + es] = v.x;
            sX[(kq * 4 + 1) * 64 + es] = v.y;
            sX[(kq * 4 + 2) * 64 + es] = v.z;
            sX[(kq * 4 + 3) * 64 + es] = v.w;
        }
        __syncthreads();

        // ---- layer 1: h1 = b1 + preA[src] + preB[dst] + rbf @ W1c ; sH1 = ssp(h1)
        {
            const int j0 = ty * 8;
            u64 acc[4][4];
            u64 b0 = *(const u64*)(sB1 + j0),     b1 = *(const u64*)(sB1 + j0 + 2);
            u64 b2v = *(const u64*)(sB1 + j0 + 4), b3 = *(const u64*)(sB1 + j0 + 6);
#pragma unroll
            for (int i = 0; i < 4; i++) { acc[i][0] = b0; acc[i][1] = b1; acc[i][2] = b2v; acc[i][3] = b3; }
            gemm_j8<true>(sX, sW1c, e0, j0, acc);
            float vals[4][8];
#pragma unroll
            for (int i = 0; i < 4; i++) {
                int s = sIdx[e0 + i], d = sIdx[64 + e0 + i];
                const float* pa = g_pre_a + (size_t)s * HN + j0;
                const float* pb = g_pre_b + (size_t)d * HN + j0;
                float4 a0 = *(const float4*)pa, a1 = *(const float4*)(pa + 4);
                float4 c0 = *(const float4*)pb, c1 = *(const float4*)(pb + 4);
                float2 v0 = unpack2(acc[i][0]), v1 = unpack2(acc[i][1]);
                float2 v2 = unpack2(acc[i][2]), v3 = unpack2(acc[i][3]);
                vals[i][0] = sspf(v0.x + a0.x + c0.x); vals[i][1] = sspf(v0.y + a0.y + c0.y);
                vals[i][2] = sspf(v1.x + a0.z + c0.z); vals[i][3] = sspf(v1.y + a0.w + c0.w);
                vals[i][4] = sspf(v2.x + a1.x + c1.x); vals[i][5] = sspf(v2.y + a1.y + c1.y);
                vals[i][6] = sspf(v3.x + a1.z + c1.z); vals[i][7] = sspf(v3.y + a1.w + c1.w);
            }
#pragma unroll
            for (int jj = 0; jj < 8; jj++)
                *(float4*)(sH1 + (j0 + jj) * 64 + e0) =
                    make_float4(vals[0][jj], vals[1][jj], vals[2][jj], vals[3][jj]);
        }
        __syncthreads();

        // ---- layer 2: new_edge = sH1 @ eu_w2 + b2 (no activation)
        {
            const int j0 = ty * 4;
            u64 acc[4][2];
            u64 b0 = *(const u64*)(sB2 + j0), b1 = *(const u64*)(sB2 + j0 + 2);
#pragma unroll
            for (int i = 0; i < 4; i++) { acc[i][0] = b0; acc[i][1] = b1; }
            gemm_j4<128>(sH1, sW2, e0, j0, acc);
            float vals[4][4];
#pragma unroll
            for (int i = 0; i < 4; i++) {
                float2 v0 = unpack2(acc[i][0]), v1 = unpack2(acc[i][1]);
                vals[i][0] = v0.x; vals[i][1] = v0.y; vals[i][2] = v1.x; vals[i][3] = v1.y;
            }
#pragma unroll
            for (int jj = 0; jj < 4; jj++)
                *(float4*)(sNE + (j0 + jj) * 64 + e0) =
                    make_float4(vals[0][jj], vals[1][jj], vals[2][jj], vals[3][jj]);
        }
        __syncthreads();

        // coalesced global write of new_edge
        {
            int e = tid >> 2;
            int jseg = (tid & 3) * 16;
            int g = base + e;
            if (g < E) {
#pragma unroll
                for (int c = 0; c < 16; c += 4) {
                    float4 v = make_float4(sNE[(jseg + c) * 64 + e], sNE[(jseg + c + 1) * 64 + e],
                                           sNE[(jseg + c + 2) * 64 + e], sNE[(jseg + c + 3) * 64 + e]);
                    *(float4*)(out_edge + (size_t)g * 64 + jseg + c) = v;
                }
            }
        }

        // ---- layer 3: t = ssp(new_edge @ pe_w1 + pe_b1)
        {
            const int j0 = ty * 4;
            u64 acc[4][2];
            u64 b0 = *(const u64*)(sPb1 + j0), b1 = *(const u64*)(sPb1 + j0 + 2);
#pragma unroll
            for (int i = 0; i < 4; i++) { acc[i][0] = b0; acc[i][1] = b1; }
            gemm_j4<64>(sNE, sPe1, e0, j0, acc);
            float vals[4][4];
#pragma unroll
            for (int i = 0; i < 4; i++) {
                float2 v0 = unpack2(acc[i][0]), v1 = unpack2(acc[i][1]);
                vals[i][0] = sspf(v0.x); vals[i][1] = sspf(v0.y);
                vals[i][2] = sspf(v1.x); vals[i][3] = sspf(v1.y);
            }
#pragma unroll
            for (int jj = 0; jj < 4; jj++)
                *(float4*)(sT + (j0 + jj) * 64 + e0) =
                    make_float4(vals[0][jj], vals[1][jj], vals[2][jj], vals[3][jj]);
        }
        __syncthreads();

        // ---- layer 4: he = t @ pe_w2 + pe_b2, atomic segment-sum at dst
        {
            const int j0 = ty * 4;
            u64 acc[4][2];
            u64 b0 = *(const u64*)(sPb2 + j0), b1 = *(const u64*)(sPb2 + j0 + 2);
#pragma unroll
            for (int i = 0; i < 4; i++) { acc[i][0] = b0; acc[i][1] = b1; }
            gemm_j4<64>(sT, sPe2, e0, j0, acc);
#pragma unroll
            for (int i = 0; i < 4; i++) {
                int g = base + e0 + i;
                if (g < E) {
                    int d = sIdx[64 + e0 + i];
                    float* ap = agg + (size_t)d * 64 + j0;
                    float2 v0 = unpack2(acc[i][0]), v1 = unpack2(acc[i][1]);
                    atomicAdd(ap + 0, v0.x); atomicAdd(ap + 1, v0.y);
                    atomicAdd(ap + 2, v1.x); atomicAdd(ap + 3, v1.y);
                }
            }
        }
        __syncthreads();
    }
}

// ---- node post: out = node_feats + ssp(agg@pn2_w1+b1)@pn2_w2+b2 (in-place on agg region)
__global__ void __launch_bounds__(256, 1)
node_post_kernel(const float* __restrict__ node_feats,
                 const float* __restrict__ w1, const float* __restrict__ b1,
                 const float* __restrict__ w2, const float* __restrict__ b2,
                 float* __restrict__ node_out, int N) {
    extern __shared__ float sm[];
    float* sW1 = sm;             // [64][64]
    float* sW2 = sm + 4096;
    float* sXT = sm + 8192;      // agg transposed
    float* sTT = sm + 12288;
    float* sB1 = sm + 16384;
    float* sB2 = sm + 16448;
    const int tid = threadIdx.x;
    for (int i = tid; i < 4096; i += 256) { sW1[i] = w1[i]; sW2[i] = w2[i]; }
    if (tid < 64) { sB1[tid] = b1[tid]; sB2[tid] = b2[tid]; }
    const int base = blockIdx.x * 64;
#pragma unroll
    for (int i = 0; i < 4; i++) {
        int lin = tid + 256 * i;
        int n = lin >> 4, kq = lin & 15;
        int g = base + n;
        float4 v = make_float4(0.f, 0.f, 0.f, 0.f);
        if (g < N) v = *(const float4*)(node_out + (size_t)g * 64 + kq * 4);
        sXT[(kq * 4 + 0) * 64 + n] = v.x;
        sXT[(kq * 4 + 1) * 64 + n] = v.y;
        sXT[(kq * 4 + 2) * 64 + n] = v.z;
        sXT[(kq * 4 + 3) * 64 + n] = v.w;
    }
    __syncthreads();
    const int tx = tid & 15, ty = tid >> 4;
    const int n0 = tx * 4, j0 = ty * 4;
    {
        u64 acc[4][2];
        u64 c0 = *(const u64*)(sB1 + j0), c1 = *(const u64*)(sB1 + j0 + 2);
#pragma unroll
        for (int i = 0; i < 4; i++) { acc[i][0] = c0; acc[i][1] = c1; }
        gemm_j4<64>(sXT, sW1, n0, j0, acc);
        float vals[4][4];
#pragma unroll
        for (int i = 0; i < 4; i++) {
            float2 v0 = unpack2(acc[i][0]), v1 = unpack2(acc[i][1]);
            vals[i][0] = sspf(v0.x); vals[i][1] = sspf(v0.y);
            vals[i][2] = sspf(v1.x); vals[i][3] = sspf(v1.y);
        }
#pragma unroll
        for (int jj = 0; jj < 4; jj++)
            *(float4*)(sTT + (j0 + jj) * 64 + n0) =
                make_float4(vals[0][jj], vals[1][jj], vals[2][jj], vals[3][jj]);
    }
    __syncthreads();
    {
        u64 acc[4][2];
        u64 c0 = *(const u64*)(sB2 + j0), c1 = *(const u64*)(sB2 + j0 + 2);
#pragma unroll
        for (int i = 0; i < 4; i++) { acc[i][0] = c0; acc[i][1] = c1; }
        gemm_j4<64>(sTT, sW2, n0, j0, acc);
#pragma unroll
        for (int i = 0; i < 4; i++) {
            int g = base + n0 + i;
            if (g < N) {
                float4 nf = *(const float4*)(node_feats + (size_t)g * 64 + j0);
                float2 v0 = unpack2(acc[i][0]), v1 = unpack2(acc[i][1]);
                *(float4*)(node_out + (size_t)g * 64 + j0) =
                    make_float4(v0.x + nf.x, v0.y + nf.y, v1.x + nf.z, v1.y + nf.w);
            }
        }
    }
}

extern "C" void kernel_launch(void* const* d_in, const int* in_sizes, int n_in,
                              void* d_out, int out_size) {
    const float* node_feats = (const float*)d_in[0];
    const float* edge_feats = (const float*)d_in[1];
    const int*   src  = (const int*)d_in[2];
    const int*   dst  = (const int*)d_in[3];
    const float* eu_w1 = (const float*)d_in[4];
    const float* eu_b1 = (const float*)d_in[5];
    const float* eu_w2 = (const float*)d_in[6];
    const float* eu_b2 = (const float*)d_in[7];
    // d_in[8], d_in[9] = pn1_w, pn1_b — computed but unused in reference forward
    const float* pe_w1 = (const float*)d_in[10];
    const float* pe_b1 = (const float*)d_in[11];
    const float* pe_w2 = (const float*)d_in[12];
    const float* pe_b2 = (const float*)d_in[13];
    const float* pn2_w1 = (const float*)d_in[14];
    const float* pn2_b1 = (const float*)d_in[15];
    const float* pn2_w2 = (const float*)d_in[16];
    const float* pn2_b2 = (const float*)d_in[17];

    const int N = in_sizes[0] / DIMN;
    const int E = in_sizes[1] / RBFN;
    float* out_node = (float*)d_out;
    float* out_edge = out_node + (size_t)N * DIMN;

    cudaFuncSetAttribute(edge_kernel, cudaFuncAttributeMaxDynamicSharedMemorySize,
                         EDGE_SMEM_FLOATS * 4);
    cudaFuncSetAttribute(node_pre_kernel, cudaFuncAttributeMaxDynamicSharedMemorySize,
                         12288 * 4);
    cudaFuncSetAttribute(node_post_kernel, cudaFuncAttributeMaxDynamicSharedMemorySize,
                         16512 * 4);

    // zero the node-aggregation region (reused as segment-sum accumulator)
    cudaMemsetAsync(out_node, 0, (size_t)N * DIMN * sizeof(float));

    dim3 gpre((N + 63) / 64, 2);
    node_pre_kernel<<<gpre, 256, 12288 * 4>>>(node_feats, eu_w1, N);

    int sms = 0;
    cudaDeviceGetAttribute(&sms, cudaDevAttrMultiProcessorCount, 0);
    if (sms <= 0) sms = 148;
    int numTiles = (E + 63) / 64;
    int grid = (sms < numTiles) ? sms : numTiles;
    edge_kernel<<<grid, 256, EDGE_SMEM_FLOATS * 4>>>(
        edge_feats, src, dst, eu_w1, eu_b1, eu_w2, eu_b2,
        pe_w1, pe_b1, pe_w2, pe_b2, out_node, out_edge, E, numTiles);

    node_post_kernel<<<(N + 63) / 64, 256, 16512 * 4>>>(
        node_feats, pn2_w1, pn2_b1, pn2_w2, pn2_b2, out_node, N);
}